// round 3
// baseline (speedup 1.0000x reference)
#include <cuda_runtime.h>
#include <cstdint>
#include <math.h>

#define D_MODEL 4096
#define N_HEADS 16
#define D_HEAD  256
#define ROTARY  64
#define D_FF    16384
#define BATCH   2
#define SEQ     2048
#define NROWS   (BATCH*SEQ)   /* 4096 */

// ---------------------------------------------------------------------------
// Scratch (static device globals; no allocation allowed)
// ---------------------------------------------------------------------------
__device__ float g_xn [(size_t)NROWS * D_MODEL];
__device__ float g_q  [(size_t)NROWS * D_MODEL];
__device__ float g_k  [(size_t)NROWS * D_MODEL];
__device__ float g_v  [(size_t)NROWS * D_MODEL];
__device__ float g_ctx[(size_t)NROWS * D_MODEL];
__device__ float g_x2 [(size_t)NROWS * D_MODEL];
__device__ float g_xn2[(size_t)NROWS * D_MODEL];
__device__ float g_sc [(size_t)BATCH * N_HEADS * SEQ * SEQ];  // 512 MB
__device__ float g_h  [(size_t)NROWS * D_FF];                 // 256 MB

// ---------------------------------------------------------------------------
// LayerNorm: one block per row (4096 cols, 256 threads x 16 elems)
// ---------------------------------------------------------------------------
__global__ void layernorm_kernel(const float* __restrict__ x,
                                 const float* __restrict__ scale,
                                 const float* __restrict__ offset,
                                 float* __restrict__ out)
{
    int row = blockIdx.x;
    const float4* xr = reinterpret_cast<const float4*>(x + (size_t)row * D_MODEL);
    float4 vals[4];
    float s = 0.f, sq = 0.f;
#pragma unroll
    for (int p = 0; p < 4; p++) {
        float4 v = xr[threadIdx.x + p * 256];
        vals[p] = v;
        s  += v.x + v.y + v.z + v.w;
        sq += v.x*v.x + v.y*v.y + v.z*v.z + v.w*v.w;
    }
    __shared__ float shm[64];
#pragma unroll
    for (int o = 16; o > 0; o >>= 1) {
        s  += __shfl_xor_sync(0xffffffffu, s,  o);
        sq += __shfl_xor_sync(0xffffffffu, sq, o);
    }
    int w = threadIdx.x >> 5;
    if ((threadIdx.x & 31) == 0) { shm[w] = s; shm[w + 32] = sq; }
    __syncthreads();
    if (threadIdx.x < 32) {
        float a = (threadIdx.x < 8) ? shm[threadIdx.x]      : 0.f;
        float b = (threadIdx.x < 8) ? shm[32 + threadIdx.x] : 0.f;
#pragma unroll
        for (int o = 4; o > 0; o >>= 1) {
            a += __shfl_xor_sync(0xffffffffu, a, o);
            b += __shfl_xor_sync(0xffffffffu, b, o);
        }
        if (threadIdx.x == 0) { shm[0] = a; shm[1] = b; }
    }
    __syncthreads();
    float mean = shm[0] * (1.0f / D_MODEL);
    float var  = shm[1] * (1.0f / D_MODEL) - mean * mean;
    float inv  = rsqrtf(var + 1e-5f);
    const float4* sc4 = reinterpret_cast<const float4*>(scale);
    const float4* of4 = reinterpret_cast<const float4*>(offset);
    float4* o4 = reinterpret_cast<float4*>(out + (size_t)row * D_MODEL);
#pragma unroll
    for (int p = 0; p < 4; p++) {
        int i = threadIdx.x + p * 256;
        float4 v = vals[p], g = sc4[i], b = of4[i], r;
        r.x = (v.x - mean) * inv * g.x + b.x;
        r.y = (v.y - mean) * inv * g.y + b.y;
        r.z = (v.z - mean) * inv * g.z + b.z;
        r.w = (v.w - mean) * inv * g.w + b.w;
        o4[i] = r;
    }
}

// ---------------------------------------------------------------------------
// RoPE on q and k (first 64 dims of each head, interleaved pairs)
// ---------------------------------------------------------------------------
__global__ void rope_kernel(float* __restrict__ q, float* __restrict__ k)
{
    const int HALF = ROTARY / 2;  // 32
    int idx = blockIdx.x * blockDim.x + threadIdx.x;
    int total = NROWS * N_HEADS * HALF;
    if (idx >= total) return;
    int i  = idx % HALF;
    int h  = (idx / HALF) % N_HEADS;
    int bt = idx / (HALF * N_HEADS);
    int t  = bt % SEQ;

    float inv_freq = powf(10000.0f, -(float)i / (float)HALF);
    float fr = (float)t * inv_freq;
    float sn, cs;
    sincosf(fr, &sn, &cs);

    size_t base = (size_t)bt * D_MODEL + (size_t)h * D_HEAD + 2 * i;
    float x1 = q[base], x2 = q[base + 1];
    q[base]     = x1 * cs - x2 * sn;
    q[base + 1] = x2 * cs + x1 * sn;
    x1 = k[base]; x2 = k[base + 1];
    k[base]     = x1 * cs - x2 * sn;
    k[base + 1] = x2 * cs + x1 * sn;
}

// ---------------------------------------------------------------------------
// Causal softmax, in-place on scores. One block per (b,h,t) row; the 2048-col
// row lives in registers (8 per thread) so it's a single read + single write.
// ---------------------------------------------------------------------------
__global__ void softmax_kernel(float* __restrict__ scores)
{
    size_t r = blockIdx.x;            // 0 .. B*H*SEQ-1
    int t = blockIdx.x % SEQ;
    float* row = scores + r * SEQ;
    const float sc = 1.0f / 16.0f;    // 1/sqrt(256)

    float v[8];
    float mx = -1e30f;
#pragma unroll
    for (int j = 0; j < 8; j++) {
        int col = threadIdx.x + j * 256;
        float xv = (col <= t) ? row[col] * sc : -1e30f;
        v[j] = xv;
        mx = fmaxf(mx, xv);
    }
    __shared__ float shm[32];
#pragma unroll
    for (int o = 16; o > 0; o >>= 1) mx = fmaxf(mx, __shfl_xor_sync(0xffffffffu, mx, o));
    if ((threadIdx.x & 31) == 0) shm[threadIdx.x >> 5] = mx;
    __syncthreads();
    if (threadIdx.x < 32) {
        float m = (threadIdx.x < 8) ? shm[threadIdx.x] : -1e30f;
#pragma unroll
        for (int o = 4; o > 0; o >>= 1) m = fmaxf(m, __shfl_xor_sync(0xffffffffu, m, o));
        if (threadIdx.x == 0) shm[0] = m;
    }
    __syncthreads();
    mx = shm[0];
    __syncthreads();   // before shm reuse

    float s = 0.f;
#pragma unroll
    for (int j = 0; j < 8; j++) { float e = expf(v[j] - mx); v[j] = e; s += e; }
#pragma unroll
    for (int o = 16; o > 0; o >>= 1) s += __shfl_xor_sync(0xffffffffu, s, o);
    if ((threadIdx.x & 31) == 0) shm[threadIdx.x >> 5] = s;
    __syncthreads();
    if (threadIdx.x < 32) {
        float a = (threadIdx.x < 8) ? shm[threadIdx.x] : 0.f;
#pragma unroll
        for (int o = 4; o > 0; o >>= 1) a += __shfl_xor_sync(0xffffffffu, a, o);
        if (threadIdx.x == 0) shm[0] = a;
    }
    __syncthreads();
    float inv = 1.0f / shm[0];
#pragma unroll
    for (int j = 0; j < 8; j++) row[threadIdx.x + j * 256] = v[j] * inv;
}

// ---------------------------------------------------------------------------
// TF32 tensor-core GEMM.  C = A @ op(B) (+ epilogue)
//   A: M x K row-major (lda).   TRANS_B=false: B is K x N row-major (ldb)
//                               TRANS_B=true : B is N x K row-major (ldb)
//   EPI: 0 none | 1 bias+gelu | 2 +residual | 3 bias+residual
//   CAUSAL_SKIP: skip tiles fully above the diagonal (scores)
//   CAUSAL_K:    truncate K-loop at the causal boundary (ctx)
//   Batched over blockIdx.z with split (b,h) strides.
// ---------------------------------------------------------------------------
#define BM 128
#define BN 128
#define BK 32
#define GEMM_THREADS 256

__device__ __forceinline__ uint32_t f2tf32(float f) {
    uint32_t u;
    asm("cvt.rna.tf32.f32 %0, %1;" : "=r"(u) : "f"(f));
    return u;
}
__device__ __forceinline__ float gelu_f(float x) {
    return 0.5f * x * (1.0f + tanhf(0.7978845608028654f * (x + 0.044715f * x * x * x)));
}

template<bool TRANS_B, int EPI, bool CAUSAL_SKIP, bool CAUSAL_K>
__global__ void __launch_bounds__(GEMM_THREADS)
gemm_tf32(const float* __restrict__ A, const float* __restrict__ Bm,
          float* __restrict__ C,
          const float* __restrict__ bias, const float* __restrict__ Res,
          int M, int N, int K, int lda, int ldb, int ldc,
          long sAb, long sAh, long sBb, long sBh, long sCb, long sCh, int Hb)
{
    int m0 = blockIdx.y * BM;
    int n0 = blockIdx.x * BN;
    if (CAUSAL_SKIP) { if (n0 > m0 + BM - 1) return; }

    int z = blockIdx.z;
    int b = z / Hb, hh = z % Hb;
    A  += (size_t)b * sAb + (size_t)hh * sAh;
    Bm += (size_t)b * sBb + (size_t)hh * sBh;
    C  += (size_t)b * sCb + (size_t)hh * sCh;

    __shared__ __align__(16) float As[BM][BK + 4];   // stride 36: conflict-free frags
    __shared__ __align__(16) float Bs[BK][BN + 8];   // stride 136: conflict-free frags

    int tid  = threadIdx.x;
    int lane = tid & 31, warp = tid >> 5;
    int wm = warp & 3, wn = warp >> 2;     // 4x2 warp grid; warp tile 32x64
    int g  = lane >> 2, tg = lane & 3;

    float acc[2][8][4];
#pragma unroll
    for (int a = 0; a < 2; a++)
#pragma unroll
        for (int c = 0; c < 8; c++)
#pragma unroll
            for (int d = 0; d < 4; d++) acc[a][c][d] = 0.f;

    int KT = K / BK;
    if (CAUSAL_K) { int lim = (m0 + BM) / BK; if (lim < KT) KT = lim; }

    int ar = tid >> 3, aq = tid & 7;       // A / NT-B load pattern (row, quad)
    int br = tid >> 5, bq = tid & 31;      // NN-B load pattern

    auto ldA = [&](int kt, float4* reg) {
        const float* Ap = A + (size_t)m0 * lda + kt * BK;
#pragma unroll
        for (int p = 0; p < 4; p++)
            reg[p] = *reinterpret_cast<const float4*>(Ap + (size_t)(ar + p * 32) * lda + aq * 4);
    };
    auto stA = [&](const float4* reg) {
#pragma unroll
        for (int p = 0; p < 4; p++) {
            float4 v = reg[p];
            uint32_t* d = reinterpret_cast<uint32_t*>(&As[ar + p * 32][aq * 4]);
            d[0] = f2tf32(v.x); d[1] = f2tf32(v.y); d[2] = f2tf32(v.z); d[3] = f2tf32(v.w);
        }
    };
    auto ldB = [&](int kt, float4* reg) {
        if (!TRANS_B) {
            const float* Bp = Bm + (size_t)(kt * BK) * ldb + n0;
#pragma unroll
            for (int p = 0; p < 4; p++)
                reg[p] = *reinterpret_cast<const float4*>(Bp + (size_t)(br + p * 8) * ldb + bq * 4);
        } else {
            const float* Bp = Bm + (size_t)n0 * ldb + kt * BK;
#pragma unroll
            for (int p = 0; p < 4; p++)
                reg[p] = *reinterpret_cast<const float4*>(Bp + (size_t)(ar + p * 32) * ldb + aq * 4);
        }
    };
    auto stB = [&](const float4* reg) {
        if (!TRANS_B) {
#pragma unroll
            for (int p = 0; p < 4; p++) {
                float4 v = reg[p];
                uint32_t* d = reinterpret_cast<uint32_t*>(&Bs[br + p * 8][bq * 4]);
                d[0] = f2tf32(v.x); d[1] = f2tf32(v.y); d[2] = f2tf32(v.z); d[3] = f2tf32(v.w);
            }
        } else {
#pragma unroll
            for (int p = 0; p < 4; p++) {
                float4 v = reg[p];
                int n = ar + p * 32;
                reinterpret_cast<uint32_t&>(Bs[aq * 4 + 0][n]) = f2tf32(v.x);
                reinterpret_cast<uint32_t&>(Bs[aq * 4 + 1][n]) = f2tf32(v.y);
                reinterpret_cast<uint32_t&>(Bs[aq * 4 + 2][n]) = f2tf32(v.z);
                reinterpret_cast<uint32_t&>(Bs[aq * 4 + 3][n]) = f2tf32(v.w);
            }
        }
    };

    float4 ra[4], rb[4];
    ldA(0, ra); ldB(0, rb);
    stA(ra);    stB(rb);
    __syncthreads();

    for (int kt = 0; kt < KT; kt++) {
        bool has_next = (kt + 1 < KT);
        if (has_next) { ldA(kt + 1, ra); ldB(kt + 1, rb); }

#pragma unroll
        for (int kk = 0; kk < 4; kk++) {
            uint32_t af[2][4], bf[8][2];
#pragma unroll
            for (int mt = 0; mt < 2; mt++) {
                int r0 = wm * 32 + mt * 16 + g;
                af[mt][0] = reinterpret_cast<uint32_t&>(As[r0    ][kk * 8 + tg]);
                af[mt][1] = reinterpret_cast<uint32_t&>(As[r0 + 8][kk * 8 + tg]);
                af[mt][2] = reinterpret_cast<uint32_t&>(As[r0    ][kk * 8 + tg + 4]);
                af[mt][3] = reinterpret_cast<uint32_t&>(As[r0 + 8][kk * 8 + tg + 4]);
            }
#pragma unroll
            for (int nt = 0; nt < 8; nt++) {
                int c0 = wn * 64 + nt * 8 + g;
                bf[nt][0] = reinterpret_cast<uint32_t&>(Bs[kk * 8 + tg    ][c0]);
                bf[nt][1] = reinterpret_cast<uint32_t&>(Bs[kk * 8 + tg + 4][c0]);
            }
#pragma unroll
            for (int mt = 0; mt < 2; mt++)
#pragma unroll
                for (int nt = 0; nt < 8; nt++) {
                    asm volatile(
                        "mma.sync.aligned.m16n8k8.row.col.f32.tf32.tf32.f32 "
                        "{%0,%1,%2,%3}, {%4,%5,%6,%7}, {%8,%9}, {%0,%1,%2,%3};\n"
                        : "+f"(acc[mt][nt][0]), "+f"(acc[mt][nt][1]),
                          "+f"(acc[mt][nt][2]), "+f"(acc[mt][nt][3])
                        : "r"(af[mt][0]), "r"(af[mt][1]), "r"(af[mt][2]), "r"(af[mt][3]),
                          "r"(bf[nt][0]), "r"(bf[nt][1]));
                }
        }
        __syncthreads();
        if (has_next) { stA(ra); stB(rb); __syncthreads(); }
    }

    // Epilogue
#pragma unroll
    for (int mt = 0; mt < 2; mt++) {
#pragma unroll
        for (int nt = 0; nt < 8; nt++) {
            int row0 = m0 + wm * 32 + mt * 16 + g;
            int col0 = n0 + wn * 64 + nt * 8 + 2 * tg;
#pragma unroll
            for (int rr = 0; rr < 2; rr++) {
                int row = row0 + rr * 8;
#pragma unroll
                for (int cc = 0; cc < 2; cc++) {
                    int c = col0 + cc;
                    float v = acc[mt][nt][rr * 2 + cc];
                    if (EPI == 1)      v = gelu_f(v + bias[c]);
                    else if (EPI == 2) v += Res[(size_t)row * ldc + c];
                    else if (EPI == 3) v += bias[c] + Res[(size_t)row * ldc + c];
                    C[(size_t)row * ldc + c] = v;
                }
            }
        }
    }
}

// ---------------------------------------------------------------------------
// Launch
// ---------------------------------------------------------------------------
extern "C" void kernel_launch(void* const* d_in, const int* in_sizes, int n_in,
                              void* d_out, int out_size)
{
    (void)in_sizes; (void)n_in; (void)out_size;
    const float* x     = (const float*)d_in[0];
    const float* lns   = (const float*)d_in[1];
    const float* lno   = (const float*)d_in[2];
    const float* wq    = (const float*)d_in[3];
    const float* wk    = (const float*)d_in[4];
    const float* wv    = (const float*)d_in[5];
    const float* wo    = (const float*)d_in[6];
    const float* w_in  = (const float*)d_in[7];
    const float* b_in  = (const float*)d_in[8];
    const float* w_out = (const float*)d_in[9];
    const float* b_out = (const float*)d_in[10];
    float* out = (float*)d_out;

    float *xn, *q, *k, *v, *sc, *ctx, *x2, *xn2, *hbuf;
    cudaGetSymbolAddress((void**)&xn,   g_xn);
    cudaGetSymbolAddress((void**)&q,    g_q);
    cudaGetSymbolAddress((void**)&k,    g_k);
    cudaGetSymbolAddress((void**)&v,    g_v);
    cudaGetSymbolAddress((void**)&sc,   g_sc);
    cudaGetSymbolAddress((void**)&ctx,  g_ctx);
    cudaGetSymbolAddress((void**)&x2,   g_x2);
    cudaGetSymbolAddress((void**)&xn2,  g_xn2);
    cudaGetSymbolAddress((void**)&hbuf, g_h);

    dim3 blk(GEMM_THREADS);

    // 1. LayerNorm
    layernorm_kernel<<<NROWS, 256>>>(x, lns, lno, xn);

    // 2. QKV projections
    dim3 gP(D_MODEL / BN, NROWS / BM, 1);
    gemm_tf32<false, 0, false, false><<<gP, blk>>>(xn, wq, q, nullptr, nullptr,
        NROWS, D_MODEL, D_MODEL, D_MODEL, D_MODEL, D_MODEL, 0, 0, 0, 0, 0, 0, 1);
    gemm_tf32<false, 0, false, false><<<gP, blk>>>(xn, wk, k, nullptr, nullptr,
        NROWS, D_MODEL, D_MODEL, D_MODEL, D_MODEL, D_MODEL, 0, 0, 0, 0, 0, 0, 1);
    gemm_tf32<false, 0, false, false><<<gP, blk>>>(xn, wv, v, nullptr, nullptr,
        NROWS, D_MODEL, D_MODEL, D_MODEL, D_MODEL, D_MODEL, 0, 0, 0, 0, 0, 0, 1);

    // 3. RoPE on q, k
    {
        int total = NROWS * N_HEADS * (ROTARY / 2);
        rope_kernel<<<(total + 255) / 256, 256>>>(q, k);
    }

    // 4. scores = q @ k^T  (batched over b,h; causal tile-skip)
    dim3 gS(SEQ / BN, SEQ / BM, BATCH * N_HEADS);
    gemm_tf32<true, 0, true, false><<<gS, blk>>>(q, k, sc, nullptr, nullptr,
        SEQ, SEQ, D_HEAD, D_MODEL, D_MODEL, SEQ,
        (long)SEQ * D_MODEL, (long)D_HEAD,
        (long)SEQ * D_MODEL, (long)D_HEAD,
        (long)N_HEADS * SEQ * SEQ, (long)SEQ * SEQ, N_HEADS);

    // 5. causal softmax (applies the 1/16 scale)
    softmax_kernel<<<BATCH * N_HEADS * SEQ, 256>>>(sc);

    // 6. ctx = probs @ v  (batched; K truncated at causal boundary)
    dim3 gC(D_HEAD / BN, SEQ / BM, BATCH * N_HEADS);
    gemm_tf32<false, 0, false, true><<<gC, blk>>>(sc, v, ctx, nullptr, nullptr,
        SEQ, D_HEAD, SEQ, SEQ, D_MODEL, D_MODEL,
        (long)N_HEADS * SEQ * SEQ, (long)SEQ * SEQ,
        (long)SEQ * D_MODEL, (long)D_HEAD,
        (long)SEQ * D_MODEL, (long)D_HEAD, N_HEADS);

    // 7. x2 = x + ctx @ wo
    gemm_tf32<false, 2, false, false><<<gP, blk>>>(ctx, wo, x2, nullptr, x,
        NROWS, D_MODEL, D_MODEL, D_MODEL, D_MODEL, D_MODEL, 0, 0, 0, 0, 0, 0, 1);

    // 8. LayerNorm 2
    layernorm_kernel<<<NROWS, 256>>>(x2, lns, lno, xn2);

    // 9. h = gelu(xn2 @ w_in + b_in)
    dim3 gF(D_FF / BN, NROWS / BM, 1);
    gemm_tf32<false, 1, false, false><<<gF, blk>>>(xn2, w_in, hbuf, b_in, nullptr,
        NROWS, D_FF, D_MODEL, D_MODEL, D_FF, D_FF, 0, 0, 0, 0, 0, 0, 1);

    // 10. out = x2 + h @ w_out + b_out
    gemm_tf32<false, 3, false, false><<<gP, blk>>>(hbuf, w_out, out, b_out, x2,
        NROWS, D_MODEL, D_FF, D_FF, D_MODEL, D_MODEL, 0, 0, 0, 0, 0, 0, 1);
}

// round 5
// speedup vs baseline: 1.3669x; 1.3669x over previous
#include <cuda_runtime.h>
#include <cstdint>
#include <math.h>

#define D_MODEL 4096
#define N_HEADS 16
#define D_HEAD  256
#define ROTARY  64
#define D_FF    16384
#define BATCH   2
#define SEQ     2048
#define NROWS   (BATCH*SEQ)   /* 4096 */

#define BN 128
#define BK 32
#define STAGES 3
#define A_STRIDE 36            /* BK + 4 pad, 16B-aligned rows */
#define B_STRIDE 136           /* BN + 8 pad */
#define BSTG 4608              /* per-stage B elems (max of 32*136=4352 and 128*36=4608) */

// ---------------------------------------------------------------------------
// Scratch (static device globals; no allocation allowed)
// ---------------------------------------------------------------------------
__device__ __align__(16) float g_xn [(size_t)NROWS * D_MODEL];
__device__ __align__(16) float g_q  [(size_t)NROWS * D_MODEL];
__device__ __align__(16) float g_k  [(size_t)NROWS * D_MODEL];
__device__ __align__(16) float g_v  [(size_t)NROWS * D_MODEL];
__device__ __align__(16) float g_ctx[(size_t)NROWS * D_MODEL];
__device__ __align__(16) float g_x2 [(size_t)NROWS * D_MODEL];
__device__ __align__(16) float g_xn2[(size_t)NROWS * D_MODEL];
__device__ __align__(16) float g_sc [(size_t)BATCH * N_HEADS * SEQ * SEQ];  // 512 MB
__device__ __align__(16) float g_h  [(size_t)NROWS * D_FF];                 // 256 MB
__device__ __align__(16) float g_wr [(size_t)201326592];                    // 768 MB tf32 weights

__device__ __forceinline__ uint32_t f2tf32(float f) {
    uint32_t u;
    asm("cvt.rna.tf32.f32 %0, %1;" : "=r"(u) : "f"(f));
    return u;
}
__device__ __forceinline__ float rtf(float f) { return __uint_as_float(f2tf32(f)); }
__device__ __forceinline__ float gelu_f(float x) {
    return 0.5f * x * (1.0f + tanhf(0.7978845608028654f * (x + 0.044715f * x * x * x)));
}
__device__ __forceinline__ void cp16(uint32_t dst, const float* src) {
    asm volatile("cp.async.cg.shared.global [%0], [%1], 16;\n" :: "r"(dst), "l"(src));
}
__device__ __forceinline__ void cp_commit() {
    asm volatile("cp.async.commit_group;\n" ::: "memory");
}
__device__ __forceinline__ void cp_wait1() {
    asm volatile("cp.async.wait_group 1;\n" ::: "memory");
}

// ---------------------------------------------------------------------------
// Round a tensor to tf32 (RNA), float4 per thread
// ---------------------------------------------------------------------------
__global__ void round_kernel(const float* __restrict__ in, float* __restrict__ out, int n4)
{
    int i = blockIdx.x * blockDim.x + threadIdx.x;
    if (i >= n4) return;
    float4 v = reinterpret_cast<const float4*>(in)[i];
    v.x = rtf(v.x); v.y = rtf(v.y); v.z = rtf(v.z); v.w = rtf(v.w);
    reinterpret_cast<float4*>(out)[i] = v;
}

// ---------------------------------------------------------------------------
// LayerNorm: one block per row; output rounded to tf32 (feeds a GEMM A-operand)
// ---------------------------------------------------------------------------
__global__ void layernorm_kernel(const float* __restrict__ x,
                                 const float* __restrict__ scale,
                                 const float* __restrict__ offset,
                                 float* __restrict__ out)
{
    int row = blockIdx.x;
    const float4* xr = reinterpret_cast<const float4*>(x + (size_t)row * D_MODEL);
    float4 vals[4];
    float s = 0.f, sq = 0.f;
#pragma unroll
    for (int p = 0; p < 4; p++) {
        float4 v = xr[threadIdx.x + p * 256];
        vals[p] = v;
        s  += v.x + v.y + v.z + v.w;
        sq += v.x*v.x + v.y*v.y + v.z*v.z + v.w*v.w;
    }
    __shared__ float shm[64];
#pragma unroll
    for (int o = 16; o > 0; o >>= 1) {
        s  += __shfl_xor_sync(0xffffffffu, s,  o);
        sq += __shfl_xor_sync(0xffffffffu, sq, o);
    }
    int w = threadIdx.x >> 5;
    if ((threadIdx.x & 31) == 0) { shm[w] = s; shm[w + 32] = sq; }
    __syncthreads();
    if (threadIdx.x < 32) {
        float a = (threadIdx.x < 8) ? shm[threadIdx.x]      : 0.f;
        float b = (threadIdx.x < 8) ? shm[32 + threadIdx.x] : 0.f;
#pragma unroll
        for (int o = 4; o > 0; o >>= 1) {
            a += __shfl_xor_sync(0xffffffffu, a, o);
            b += __shfl_xor_sync(0xffffffffu, b, o);
        }
        if (threadIdx.x == 0) { shm[0] = a; shm[1] = b; }
    }
    __syncthreads();
    float mean = shm[0] * (1.0f / D_MODEL);
    float var  = shm[1] * (1.0f / D_MODEL) - mean * mean;
    float inv  = rsqrtf(var + 1e-5f);
    const float4* sc4 = reinterpret_cast<const float4*>(scale);
    const float4* of4 = reinterpret_cast<const float4*>(offset);
    float4* o4 = reinterpret_cast<float4*>(out + (size_t)row * D_MODEL);
#pragma unroll
    for (int p = 0; p < 4; p++) {
        int i = threadIdx.x + p * 256;
        float4 v = vals[p], g = sc4[i], b = of4[i], r;
        r.x = rtf((v.x - mean) * inv * g.x + b.x);
        r.y = rtf((v.y - mean) * inv * g.y + b.y);
        r.z = rtf((v.z - mean) * inv * g.z + b.z);
        r.w = rtf((v.w - mean) * inv * g.w + b.w);
        o4[i] = r;
    }
}

// ---------------------------------------------------------------------------
// RoPE (rounds rotated outputs back to tf32)
// ---------------------------------------------------------------------------
__global__ void rope_kernel(float* __restrict__ q, float* __restrict__ k)
{
    const int HALF = ROTARY / 2;
    int idx = blockIdx.x * blockDim.x + threadIdx.x;
    int total = NROWS * N_HEADS * HALF;
    if (idx >= total) return;
    int i  = idx % HALF;
    int h  = (idx / HALF) % N_HEADS;
    int bt = idx / (HALF * N_HEADS);
    int t  = bt % SEQ;

    float inv_freq = powf(10000.0f, -(float)i / (float)HALF);
    float fr = (float)t * inv_freq;
    float sn, cs;
    sincosf(fr, &sn, &cs);

    size_t base = (size_t)bt * D_MODEL + (size_t)h * D_HEAD + 2 * i;
    float x1 = q[base], x2 = q[base + 1];
    q[base]     = rtf(x1 * cs - x2 * sn);
    q[base + 1] = rtf(x2 * cs + x1 * sn);
    x1 = k[base]; x2 = k[base + 1];
    k[base]     = rtf(x1 * cs - x2 * sn);
    k[base + 1] = rtf(x2 * cs + x1 * sn);
}

// ---------------------------------------------------------------------------
// Causal softmax, in-place; writes tf32-rounded probabilities.
// Chunks fully beyond the causal tile boundary ((t>>7)+1)*128 are never read
// by the K-truncated ctx GEMM, so we skip those writes entirely.
// ---------------------------------------------------------------------------
__global__ void softmax_kernel(float* __restrict__ scores)
{
    size_t r = blockIdx.x;
    int t = blockIdx.x % SEQ;
    float* row = scores + r * SEQ;
    const float sc = 1.0f / 16.0f;
    int bound = ((t >> 7) + 1) << 7;   // multiple of 128; ctx GEMM reads cols < bound

    float v[8];
    float mx = -1e30f;
#pragma unroll
    for (int j = 0; j < 8; j++) {
        int col = threadIdx.x + j * 256;
        float xv = (col <= t) ? row[col] * sc : -1e30f;
        v[j] = xv;
        mx = fmaxf(mx, xv);
    }
    __shared__ float shm[32];
#pragma unroll
    for (int o = 16; o > 0; o >>= 1) mx = fmaxf(mx, __shfl_xor_sync(0xffffffffu, mx, o));
    if ((threadIdx.x & 31) == 0) shm[threadIdx.x >> 5] = mx;
    __syncthreads();
    if (threadIdx.x < 32) {
        float m = (threadIdx.x < 8) ? shm[threadIdx.x] : -1e30f;
#pragma unroll
        for (int o = 4; o > 0; o >>= 1) m = fmaxf(m, __shfl_xor_sync(0xffffffffu, m, o));
        if (threadIdx.x == 0) shm[0] = m;
    }
    __syncthreads();
    mx = shm[0];
    __syncthreads();

    float s = 0.f;
#pragma unroll
    for (int j = 0; j < 8; j++) { float e = expf(v[j] - mx); v[j] = e; s += e; }
#pragma unroll
    for (int o = 16; o > 0; o >>= 1) s += __shfl_xor_sync(0xffffffffu, s, o);
    if ((threadIdx.x & 31) == 0) shm[threadIdx.x >> 5] = s;
    __syncthreads();
    if (threadIdx.x < 32) {
        float a = (threadIdx.x < 8) ? shm[threadIdx.x] : 0.f;
#pragma unroll
        for (int o = 4; o > 0; o >>= 1) a += __shfl_xor_sync(0xffffffffu, a, o);
        if (threadIdx.x == 0) shm[0] = a;
    }
    __syncthreads();
    float inv = 1.0f / shm[0];
#pragma unroll
    for (int j = 0; j < 8; j++) {
        if (j * 256 < bound)
            row[threadIdx.x + j * 256] = rtf(v[j] * inv);
    }
}

// ---------------------------------------------------------------------------
// TF32 tensor-core GEMM, cp.async 3-stage pipeline.
//   Inputs must already be tf32-rounded (producers handle this).
//   BMT in {128, 256}.  Warp grid 4x2; warp tile (BMT/4) x 64.
//   EPI: 0 none | 1 bias+gelu | 2 +residual | 3 bias+residual
//   ROUNDOUT: round C to tf32 (output feeds another GEMM)
// ---------------------------------------------------------------------------
template<int BMT, bool TRANS_B, int EPI, bool ROUNDOUT, bool CAUSAL_SKIP, bool CAUSAL_K>
__global__ void __launch_bounds__(256)
gemm_tf32(const float* __restrict__ A, const float* __restrict__ Bm,
          float* __restrict__ C,
          const float* __restrict__ bias, const float* __restrict__ Res,
          int M, int N, int K, int lda, int ldb, int ldc,
          long sAb, long sAh, long sBb, long sBh, long sCb, long sCh, int Hb)
{
    constexpr int MT   = BMT / 128;       // 1 or 2
    constexpr int ASTG = BMT * A_STRIDE;  // per-stage A elems

    int m0 = blockIdx.y * BMT;
    int n0 = blockIdx.x * BN;
    if (CAUSAL_SKIP) { if (n0 > m0 + BMT - 1) return; }

    int z = blockIdx.z;
    int b = z / Hb, hh = z % Hb;
    A  += (size_t)b * sAb + (size_t)hh * sAh;
    Bm += (size_t)b * sBb + (size_t)hh * sBh;
    C  += (size_t)b * sCb + (size_t)hh * sCh;

    extern __shared__ float smem_dyn[];
    float* AsF = smem_dyn;
    float* BsF = smem_dyn + STAGES * ASTG;
    uint32_t aBase = (uint32_t)__cvta_generic_to_shared(AsF);
    uint32_t bBase = (uint32_t)__cvta_generic_to_shared(BsF);

    int tid = threadIdx.x;
    int lane = tid & 31, warp = tid >> 5;
    int wm = warp & 3, wn = warp >> 2;
    int g  = lane >> 2, tg = lane & 3;

    float acc[2 * MT][8][4] = {};

    int KT = K / BK;
    if (CAUSAL_K) { int lim = (m0 + BMT) / BK; if (lim < KT) KT = lim; }

    int ar = tid >> 3, aq = tid & 7;
    int br = tid >> 5, bq = tid & 31;

    auto loadTile = [&](int kt, int s) {
        const float* Ap = A + (size_t)(m0 + ar) * lda + (size_t)kt * BK + aq * 4;
#pragma unroll
        for (int p = 0; p < BMT / 32; p++)
            cp16(aBase + ((s * ASTG + (ar + p * 32) * A_STRIDE + aq * 4) << 2),
                 Ap + (size_t)p * 32 * lda);
        if (!TRANS_B) {
            const float* Bp = Bm + (size_t)(kt * BK + br) * ldb + n0 + bq * 4;
#pragma unroll
            for (int p = 0; p < 4; p++)
                cp16(bBase + ((s * BSTG + (br + p * 8) * B_STRIDE + bq * 4) << 2),
                     Bp + (size_t)p * 8 * ldb);
        } else {
            const float* Bp = Bm + (size_t)(n0 + ar) * ldb + (size_t)kt * BK + aq * 4;
#pragma unroll
            for (int p = 0; p < 4; p++)
                cp16(bBase + ((s * BSTG + (ar + p * 32) * A_STRIDE + aq * 4) << 2),
                     Bp + (size_t)p * 32 * ldb);
        }
    };

    // Prologue: prefetch 2 stages (empty commits keep pending-group count uniform)
    loadTile(0, 0); cp_commit();
    if (KT > 1) loadTile(1, 1);
    cp_commit();

    for (int kt = 0; kt < KT; kt++) {
        cp_wait1();            // stage kt%3 complete
        __syncthreads();
        int s = kt % STAGES;
        const uint32_t* Ast = reinterpret_cast<const uint32_t*>(AsF + s * ASTG);
        const uint32_t* Bst = reinterpret_cast<const uint32_t*>(BsF + s * BSTG);

#pragma unroll
        for (int kk = 0; kk < 4; kk++) {
            uint32_t af[2 * MT][4], bf[8][2];
#pragma unroll
            for (int mt = 0; mt < 2 * MT; mt++) {
                int r0 = wm * (32 * MT) + mt * 16 + g;
                af[mt][0] = Ast[r0 * A_STRIDE + kk * 8 + tg];
                af[mt][1] = Ast[(r0 + 8) * A_STRIDE + kk * 8 + tg];
                af[mt][2] = Ast[r0 * A_STRIDE + kk * 8 + tg + 4];
                af[mt][3] = Ast[(r0 + 8) * A_STRIDE + kk * 8 + tg + 4];
            }
#pragma unroll
            for (int nt = 0; nt < 8; nt++) {
                int c0 = wn * 64 + nt * 8 + g;
                if (!TRANS_B) {
                    bf[nt][0] = Bst[(kk * 8 + tg) * B_STRIDE + c0];
                    bf[nt][1] = Bst[(kk * 8 + tg + 4) * B_STRIDE + c0];
                } else {
                    bf[nt][0] = Bst[c0 * A_STRIDE + kk * 8 + tg];
                    bf[nt][1] = Bst[c0 * A_STRIDE + kk * 8 + tg + 4];
                }
            }
#pragma unroll
            for (int mt = 0; mt < 2 * MT; mt++)
#pragma unroll
                for (int nt = 0; nt < 8; nt++) {
                    asm volatile(
                        "mma.sync.aligned.m16n8k8.row.col.f32.tf32.tf32.f32 "
                        "{%0,%1,%2,%3}, {%4,%5,%6,%7}, {%8,%9}, {%0,%1,%2,%3};\n"
                        : "+f"(acc[mt][nt][0]), "+f"(acc[mt][nt][1]),
                          "+f"(acc[mt][nt][2]), "+f"(acc[mt][nt][3])
                        : "r"(af[mt][0]), "r"(af[mt][1]), "r"(af[mt][2]), "r"(af[mt][3]),
                          "r"(bf[nt][0]), "r"(bf[nt][1]));
                }
        }

        if (kt + 2 < KT) loadTile(kt + 2, (kt + 2) % STAGES);
        cp_commit();           // unconditional: keeps pending-group count uniform
    }

    // Epilogue (float2 stores)
#pragma unroll
    for (int mt = 0; mt < 2 * MT; mt++) {
#pragma unroll
        for (int nt = 0; nt < 8; nt++) {
            int row0 = m0 + wm * (32 * MT) + mt * 16 + g;
            int col  = n0 + wn * 64 + nt * 8 + 2 * tg;
#pragma unroll
            for (int rr = 0; rr < 2; rr++) {
                int row = row0 + rr * 8;
                float v0 = acc[mt][nt][rr * 2 + 0];
                float v1 = acc[mt][nt][rr * 2 + 1];
                if (EPI == 1) {
                    v0 = gelu_f(v0 + bias[col]);
                    v1 = gelu_f(v1 + bias[col + 1]);
                } else if (EPI == 2) {
                    float2 rv = *reinterpret_cast<const float2*>(&Res[(size_t)row * ldc + col]);
                    v0 += rv.x; v1 += rv.y;
                } else if (EPI == 3) {
                    float2 rv = *reinterpret_cast<const float2*>(&Res[(size_t)row * ldc + col]);
                    v0 += bias[col] + rv.x; v1 += bias[col + 1] + rv.y;
                }
                if (ROUNDOUT) { v0 = rtf(v0); v1 = rtf(v1); }
                float2 ov; ov.x = v0; ov.y = v1;
                *reinterpret_cast<float2*>(&C[(size_t)row * ldc + col]) = ov;
            }
        }
    }
}

// ---------------------------------------------------------------------------
// Launch
// ---------------------------------------------------------------------------
extern "C" void kernel_launch(void* const* d_in, const int* in_sizes, int n_in,
                              void* d_out, int out_size)
{
    (void)in_sizes; (void)n_in; (void)out_size;
    const float* x     = (const float*)d_in[0];
    const float* lns   = (const float*)d_in[1];
    const float* lno   = (const float*)d_in[2];
    const float* wq    = (const float*)d_in[3];
    const float* wk    = (const float*)d_in[4];
    const float* wv    = (const float*)d_in[5];
    const float* wo    = (const float*)d_in[6];
    const float* w_in  = (const float*)d_in[7];
    const float* b_in  = (const float*)d_in[8];
    const float* w_out = (const float*)d_in[9];
    const float* b_out = (const float*)d_in[10];
    float* out = (float*)d_out;

    float *xn, *q, *k, *v, *sc, *ctx, *x2, *xn2, *hbuf, *wr;
    cudaGetSymbolAddress((void**)&xn,   g_xn);
    cudaGetSymbolAddress((void**)&q,    g_q);
    cudaGetSymbolAddress((void**)&k,    g_k);
    cudaGetSymbolAddress((void**)&v,    g_v);
    cudaGetSymbolAddress((void**)&sc,   g_sc);
    cudaGetSymbolAddress((void**)&ctx,  g_ctx);
    cudaGetSymbolAddress((void**)&x2,   g_x2);
    cudaGetSymbolAddress((void**)&xn2,  g_xn2);
    cudaGetSymbolAddress((void**)&hbuf, g_h);
    cudaGetSymbolAddress((void**)&wr,   g_wr);

    const size_t WSZ = (size_t)D_MODEL * D_MODEL;        // 16,777,216
    float* wq_r  = wr;
    float* wk_r  = wr + WSZ;
    float* wv_r  = wr + 2 * WSZ;
    float* wo_r  = wr + 3 * WSZ;
    float* win_r = wr + 4 * WSZ;
    float* wou_r = win_r + (size_t)D_MODEL * D_FF;

    const int SM128 = STAGES * (128 * A_STRIDE + BSTG) * 4;   // 110592
    const int SM256 = STAGES * (256 * A_STRIDE + BSTG) * 4;   // 165888

    cudaFuncSetAttribute(gemm_tf32<256,false,0,true ,false,false>, cudaFuncAttributeMaxDynamicSharedMemorySize, SM256);
    cudaFuncSetAttribute(gemm_tf32<128,true ,0,false,true ,false>, cudaFuncAttributeMaxDynamicSharedMemorySize, SM128);
    cudaFuncSetAttribute(gemm_tf32<128,false,0,true ,false,true >, cudaFuncAttributeMaxDynamicSharedMemorySize, SM128);
    cudaFuncSetAttribute(gemm_tf32<256,false,2,false,false,false>, cudaFuncAttributeMaxDynamicSharedMemorySize, SM256);
    cudaFuncSetAttribute(gemm_tf32<256,false,1,true ,false,false>, cudaFuncAttributeMaxDynamicSharedMemorySize, SM256);
    cudaFuncSetAttribute(gemm_tf32<256,false,3,false,false,false>, cudaFuncAttributeMaxDynamicSharedMemorySize, SM256);

    dim3 blk(256);

    // 0. Round weights to tf32 once per call
    {
        int n4a = (int)(WSZ / 4);
        int n4b = (int)(((size_t)D_MODEL * D_FF) / 4);
        round_kernel<<<(n4a + 255) / 256, 256>>>(wq,    wq_r,  n4a);
        round_kernel<<<(n4a + 255) / 256, 256>>>(wk,    wk_r,  n4a);
        round_kernel<<<(n4a + 255) / 256, 256>>>(wv,    wv_r,  n4a);
        round_kernel<<<(n4a + 255) / 256, 256>>>(wo,    wo_r,  n4a);
        round_kernel<<<(n4b + 255) / 256, 256>>>(w_in,  win_r, n4b);
        round_kernel<<<(n4b + 255) / 256, 256>>>(w_out, wou_r, n4b);
    }

    // 1. LayerNorm (emits tf32)
    layernorm_kernel<<<NROWS, 256>>>(x, lns, lno, xn);

    // 2. QKV projections (round outputs: feed scores/ctx GEMMs)
    dim3 gP(D_MODEL / BN, NROWS / 256, 1);
    gemm_tf32<256,false,0,true,false,false><<<gP, blk, SM256>>>(xn, wq_r, q, nullptr, nullptr,
        NROWS, D_MODEL, D_MODEL, D_MODEL, D_MODEL, D_MODEL, 0, 0, 0, 0, 0, 0, 1);
    gemm_tf32<256,false,0,true,false,false><<<gP, blk, SM256>>>(xn, wk_r, k, nullptr, nullptr,
        NROWS, D_MODEL, D_MODEL, D_MODEL, D_MODEL, D_MODEL, 0, 0, 0, 0, 0, 0, 1);
    gemm_tf32<256,false,0,true,false,false><<<gP, blk, SM256>>>(xn, wv_r, v, nullptr, nullptr,
        NROWS, D_MODEL, D_MODEL, D_MODEL, D_MODEL, D_MODEL, 0, 0, 0, 0, 0, 0, 1);

    // 3. RoPE
    {
        int total = NROWS * N_HEADS * (ROTARY / 2);
        rope_kernel<<<(total + 255) / 256, 256>>>(q, k);
    }

    // 4. scores = q @ k^T (causal tile-skip)
    dim3 gS(SEQ / BN, SEQ / 128, BATCH * N_HEADS);
    gemm_tf32<128,true,0,false,true,false><<<gS, blk, SM128>>>(q, k, sc, nullptr, nullptr,
        SEQ, SEQ, D_HEAD, D_MODEL, D_MODEL, SEQ,
        (long)SEQ * D_MODEL, (long)D_HEAD,
        (long)SEQ * D_MODEL, (long)D_HEAD,
        (long)N_HEADS * SEQ * SEQ, (long)SEQ * SEQ, N_HEADS);

    // 5. causal softmax (emits tf32 probs; skips never-read chunks)
    softmax_kernel<<<BATCH * N_HEADS * SEQ, 256>>>(sc);

    // 6. ctx = probs @ v (K truncated at causal boundary; round: feeds WO GEMM)
    dim3 gC(D_HEAD / BN, SEQ / 128, BATCH * N_HEADS);
    gemm_tf32<128,false,0,true,false,true><<<gC, blk, SM128>>>(sc, v, ctx, nullptr, nullptr,
        SEQ, D_HEAD, SEQ, SEQ, D_MODEL, D_MODEL,
        (long)N_HEADS * SEQ * SEQ, (long)SEQ * SEQ,
        (long)SEQ * D_MODEL, (long)D_HEAD,
        (long)SEQ * D_MODEL, (long)D_HEAD, N_HEADS);

    // 7. x2 = x + ctx @ wo (fp32 residual path)
    gemm_tf32<256,false,2,false,false,false><<<gP, blk, SM256>>>(ctx, wo_r, x2, nullptr, x,
        NROWS, D_MODEL, D_MODEL, D_MODEL, D_MODEL, D_MODEL, 0, 0, 0, 0, 0, 0, 1);

    // 8. LayerNorm 2 (emits tf32)
    layernorm_kernel<<<NROWS, 256>>>(x2, lns, lno, xn2);

    // 9. h = gelu(xn2 @ w_in + b_in) (round: feeds w_out GEMM)
    dim3 gF(D_FF / BN, NROWS / 256, 1);
    gemm_tf32<256,false,1,true,false,false><<<gF, blk, SM256>>>(xn2, win_r, hbuf, b_in, nullptr,
        NROWS, D_FF, D_MODEL, D_MODEL, D_FF, D_FF, 0, 0, 0, 0, 0, 0, 1);

    // 10. out = x2 + h @ w_out + b_out
    gemm_tf32<256,false,3,false,false,false><<<gP, blk, SM256>>>(hbuf, wou_r, out, b_out, x2,
        NROWS, D_MODEL, D_FF, D_FF, D_MODEL, D_MODEL, 0, 0, 0, 0, 0, 0, 1);
}